// round 3
// baseline (speedup 1.0000x reference)
#include <cuda_runtime.h>
#include <cuda_bf16.h>
#include <cstdint>

// Problem constants
// x: [16,1,256,256]  W_cs: [256,1,32,32]  W_init: [1024,256,1,1]
// W_first: [64,1,3,3] W_blk: [64,64,3,3]  W_last: [1,64,3,3]  a_main,a_blk: [1]
// outputs: out [16,1,256,256] | outcsy [16,256,8,8] | out_initrec [16,1,256,256]

#define NBATCH 16
#define HW     256
#define PLANE  65536            // 256*256
#define CHANS  64

#define OUT_OFF 0
#define CSY_OFF 1048576
#define IR_OFF  1310720

#define F_PRELU 1
#define F_RES   2

// 268 MB each: ping-pong feature maps [16][64][256][256]
__device__ float g_featA[NBATCH * CHANS * PLANE];
__device__ float g_featB[NBATCH * CHANS * PLANE];

// ---------------------------------------------------------------------------
// Kernel 1: CS sampling conv. outcsy[n][oc][by][bx] = <x 32x32 patch, W_cs[oc]>
// grid (16 n, 8 by), 256 threads (t = oc). smem: 32 input rows + 64-k weight tile
// ---------------------------------------------------------------------------
__global__ __launch_bounds__(256) void cs_k(const float* __restrict__ x,
                                            const float* __restrict__ Wcs,
                                            float* __restrict__ csy)
{
    extern __shared__ float sm1[];
    float* xs  = sm1;          // 8192 floats: rows [by*32 .. by*32+31] x 256
    float* wsm = sm1 + 8192;   // 16384 floats: [kk][oc] for current k-chunk

    const int t  = threadIdx.x;
    const int n  = blockIdx.x;
    const int by = blockIdx.y;

    const float* xrow = x + (n << 16) + (by << 5) * 256;
    for (int i = t; i < 8192; i += 256) xs[i] = xrow[i];

    float acc[8];
#pragma unroll
    for (int bx = 0; bx < 8; bx++) acc[bx] = 0.f;

    const float* wthr = Wcs + t * 1024;
    for (int kc = 0; kc < 1024; kc += 64) {
        __syncthreads();
#pragma unroll 8
        for (int kk = 0; kk < 64; kk++) wsm[kk * 256 + t] = wthr[kc + kk];
        __syncthreads();
#pragma unroll 4
        for (int kk = 0; kk < 64; kk++) {
            const float w = wsm[kk * 256 + t];
            const int k = kc + kk;
            const float* xp = &xs[((k >> 5) << 8) + (k & 31)];
#pragma unroll
            for (int bx = 0; bx < 8; bx++) acc[bx] = fmaf(w, xp[bx << 5], acc[bx]);
        }
    }
    float* o = csy + (n * 256 + t) * 64 + (by << 3);
#pragma unroll
    for (int bx = 0; bx < 8; bx++) o[bx] = acc[bx];
}

// ---------------------------------------------------------------------------
// Kernel 2: 1x1 init conv (256 -> 1024 ch) + depth-to-space scatter.
// channel c = j*32+i  ->  initrec[n, h*32+i, w*32+j]
// grid (16 n, 4 ocg), 256 threads (oc = ocg*256+t). smem: full outcsy[n] 64KB.
// ---------------------------------------------------------------------------
__global__ __launch_bounds__(256) void init_k(const float* __restrict__ csy,
                                              const float* __restrict__ Wi,
                                              float* __restrict__ irec)
{
    extern __shared__ float cs[];    // [256 c][64 pos]
    const int t = threadIdx.x;
    const int n = blockIdx.x;
    const int oc = blockIdx.y * 256 + t;

    const float* src = csy + n * 16384;
    for (int i = t; i < 16384; i += 256) cs[i] = src[i];
    __syncthreads();

    const float* wrow = Wi + oc * 256;
    const int ii = oc & 31;          // i
    const int jj = oc >> 5;          // j
    float* dst = irec + (n << 16);

#pragma unroll
    for (int pb = 0; pb < 64; pb += 32) {
        float acc[32];
#pragma unroll
        for (int p = 0; p < 32; p++) acc[p] = 0.f;
#pragma unroll 2
        for (int c = 0; c < 256; c++) {
            const float w = wrow[c];
            const float4* cp = (const float4*)&cs[c * 64 + pb];
#pragma unroll
            for (int p4 = 0; p4 < 8; p4++) {
                const float4 v = cp[p4];
                acc[p4 * 4 + 0] = fmaf(w, v.x, acc[p4 * 4 + 0]);
                acc[p4 * 4 + 1] = fmaf(w, v.y, acc[p4 * 4 + 1]);
                acc[p4 * 4 + 2] = fmaf(w, v.z, acc[p4 * 4 + 2]);
                acc[p4 * 4 + 3] = fmaf(w, v.w, acc[p4 * 4 + 3]);
            }
        }
#pragma unroll
        for (int p = 0; p < 32; p++) {
            const int pos = pb + p;
            const int h = pos >> 3, wq = pos & 7;
            dst[(h * 32 + ii) * 256 + wq * 32 + jj] = acc[p];
        }
    }
}

// ---------------------------------------------------------------------------
// Kernel 3: generic 3x3 conv, OC=64, Cin runtime (1 or 64), pad=1.
// Tile 64(w) x 4(h). 256 threads: strip = t&31 (4 rows x 8 x-strips of 8 px),
// ocg = t>>5 (8 oc-groups of 8). Each thread: 8 oc x 8 px accumulators.
// Weights fully staged in smem (Cin*576 floats). Input tile single-buffered
// with one-channel register prefetch. Epilogue: optional residual add + PReLU,
// fully coalesced float4 stores.
// ---------------------------------------------------------------------------
__global__ __launch_bounds__(256) void conv3x3_k(
    const float* __restrict__ in, const float* __restrict__ wgt,
    const float* __restrict__ res, const float* __restrict__ alpha_p,
    float* __restrict__ out, int Cin, int flags)
{
    extern __shared__ float sm3[];
    float* ws   = sm3;                 // Cin*576
    float* tile = sm3 + Cin * 576;     // 6*66 = 396

    const int t  = threadIdx.x;
    const int n  = blockIdx.z;
    const int y0 = blockIdx.y << 2;
    const int x0 = blockIdx.x << 6;

    const int wtot = Cin * 576;
    for (int i = t; i < wtot; i += 256) ws[i] = wgt[i];

    const int strip = t & 31;
    const int ocg   = t >> 5;
    const int sy    = strip >> 3;
    const int sxb   = (strip & 7) << 3;

    float acc[8][8];
#pragma unroll
    for (int o = 0; o < 8; o++)
#pragma unroll
        for (int p = 0; p < 8; p++) acc[o][p] = 0.f;

    const float* inN = in + (size_t)n * Cin * PLANE;
    const int Cin9 = Cin * 9;

    // precompute tile-load coordinates for this thread (2 elems: t, t+256)
    const int r0i = t / 66, c0i = t - r0i * 66;
    const int gy0 = y0 - 1 + r0i, gx0 = x0 - 1 + c0i;
    const bool ok0 = ((unsigned)gy0 < 256u) && ((unsigned)gx0 < 256u);
    const int off0 = gy0 * 256 + gx0;
    const int idx1 = t + 256;
    const bool has1 = idx1 < 396;
    const int r1i = idx1 / 66, c1i = idx1 - r1i * 66;
    const int gy1 = y0 - 1 + r1i, gx1 = x0 - 1 + c1i;
    const bool ok1 = has1 && ((unsigned)gy1 < 256u) && ((unsigned)gx1 < 256u);
    const int off1 = gy1 * 256 + gx1;

    float v0 = ok0 ? inN[off0] : 0.f;
    float v1 = ok1 ? inN[off1] : 0.f;

    for (int ic = 0; ic < Cin; ic++) {
        __syncthreads();                 // previous compute done -> safe to overwrite
        tile[t] = v0;
        if (has1) tile[idx1] = v1;
        __syncthreads();
        if (ic + 1 < Cin) {              // prefetch next channel during compute
            const float* nx = inN + (ic + 1) * PLANE;
            v0 = ok0 ? nx[off0] : 0.f;
            v1 = ok1 ? nx[off1] : 0.f;
        }
        const float* wic = ws + (ocg << 3) * Cin9 + ic * 9;
#pragma unroll
        for (int ky = 0; ky < 3; ky++) {
#pragma unroll
            for (int kx = 0; kx < 3; kx++) {
                float inr[8];
                const float* tp = &tile[(sy + ky) * 66 + sxb + kx];
#pragma unroll
                for (int p = 0; p < 8; p++) inr[p] = tp[p];
#pragma unroll
                for (int o = 0; o < 8; o++) {
                    const float wv = wic[o * Cin9 + ky * 3 + kx];
#pragma unroll
                    for (int p = 0; p < 8; p++)
                        acc[o][p] = fmaf(wv, inr[p], acc[o][p]);
                }
            }
        }
    }

    const float alpha = *alpha_p;
    const int y = y0 + sy, xb = x0 + sxb;
#pragma unroll
    for (int o = 0; o < 8; o++) {
        const int oc = (ocg << 3) + o;
        const size_t gbase = (((size_t)(n * CHANS + oc)) << 16) + y * 256 + xb;
        float v[8];
#pragma unroll
        for (int p = 0; p < 8; p++) v[p] = acc[o][p];
        if (flags & F_RES) {
            const float4* rp = (const float4*)(res + gbase);
            const float4 r0 = rp[0], r1 = rp[1];
            v[0] += r0.x; v[1] += r0.y; v[2] += r0.z; v[3] += r0.w;
            v[4] += r1.x; v[5] += r1.y; v[6] += r1.z; v[7] += r1.w;
        }
        if (flags & F_PRELU) {
#pragma unroll
            for (int p = 0; p < 8; p++) v[p] = v[p] >= 0.f ? v[p] : alpha * v[p];
        }
        float4* op = (float4*)(out + gbase);
        op[0] = make_float4(v[0], v[1], v[2], v[3]);
        op[1] = make_float4(v[4], v[5], v[6], v[7]);
    }
}

// ---------------------------------------------------------------------------
// Kernel 4: last conv: out = conv3x3(feat + broadcast(initrec), W_last).
// Broadcast add folded as a 65th input channel with weights wsum[tap]=sum_c W[c][tap].
// Tile 128(w) x 16(h), 256 threads, 1 px-strip of 8 per thread, OC=1.
// ---------------------------------------------------------------------------
__global__ __launch_bounds__(256) void last_k(const float* __restrict__ fin,
                                              const float* __restrict__ irec,
                                              const float* __restrict__ Wl,
                                              float* __restrict__ out)
{
    __shared__ float ws[585];     // [64 ch][9] + wsum[9]
    __shared__ float tile[2340];  // 18 rows x 130

    const int t  = threadIdx.x;
    const int n  = blockIdx.z;
    const int y0 = blockIdx.y << 4;
    const int x0 = blockIdx.x << 7;

    for (int i = t; i < 576; i += 256) ws[i] = Wl[i];
    __syncthreads();
    if (t < 9) {
        float s = 0.f;
        for (int ic = 0; ic < 64; ic++) s += ws[ic * 9 + t];
        ws[576 + t] = s;
    }

    const int sy  = t >> 4;
    const int sxb = (t & 15) << 3;

    // tile-load coordinates (10 elems per thread)
    int offv[10]; bool okv[10]; bool hasv[10]; int idxv[10];
#pragma unroll
    for (int k = 0; k < 10; k++) {
        const int idx = t + k * 256;
        idxv[k] = idx;
        hasv[k] = idx < 2340;
        const int r = idx / 130, c = idx - r * 130;
        const int gy = y0 - 1 + r, gx = x0 - 1 + c;
        okv[k] = hasv[k] && ((unsigned)gy < 256u) && ((unsigned)gx < 256u);
        offv[k] = gy * 256 + gx;
    }

    float acc[8];
#pragma unroll
    for (int p = 0; p < 8; p++) acc[p] = 0.f;

    // prefetch channel 0
    const float* src = fin + ((size_t)(n * CHANS) << 16);
    float pf[10];
#pragma unroll
    for (int k = 0; k < 10; k++) pf[k] = okv[k] ? src[offv[k]] : 0.f;

    for (int ic = 0; ic < 65; ic++) {
        __syncthreads();
#pragma unroll
        for (int k = 0; k < 10; k++) if (hasv[k]) tile[idxv[k]] = pf[k];
        __syncthreads();
        if (ic + 1 < 65) {
            const float* nx = (ic + 1 < 64)
                ? (fin + ((size_t)(n * CHANS + ic + 1) << 16))
                : (irec + ((size_t)n << 16));
#pragma unroll
            for (int k = 0; k < 10; k++) pf[k] = okv[k] ? nx[offv[k]] : 0.f;
        }
        float w[9];
#pragma unroll
        for (int q = 0; q < 9; q++) w[q] = ws[ic * 9 + q];
#pragma unroll
        for (int ky = 0; ky < 3; ky++) {
            float rv[10];
            const float* tp = &tile[(sy + ky) * 130 + sxb];
#pragma unroll
            for (int j = 0; j < 10; j++) rv[j] = tp[j];
#pragma unroll
            for (int kx = 0; kx < 3; kx++)
#pragma unroll
                for (int p = 0; p < 8; p++)
                    acc[p] = fmaf(rv[p + kx], w[ky * 3 + kx], acc[p]);
        }
    }

    const int y = y0 + sy, xb = x0 + sxb;
    float4* op = (float4*)(out + ((size_t)n << 16) + y * 256 + xb);
    op[0] = make_float4(acc[0], acc[1], acc[2], acc[3]);
    op[1] = make_float4(acc[4], acc[5], acc[6], acc[7]);
}

// ---------------------------------------------------------------------------
extern "C" void kernel_launch(void* const* d_in, const int* in_sizes, int n_in,
                              void* d_out_, int out_size)
{
    const float* x   = (const float*)d_in[0];
    const float* Wcs = (const float*)d_in[1];
    const float* Wi  = (const float*)d_in[2];
    const float* Wf  = (const float*)d_in[3];
    const float* Wb  = (const float*)d_in[4];
    const float* Wl  = (const float*)d_in[5];
    const float* am  = (const float*)d_in[6];
    const float* ab  = (const float*)d_in[7];

    float* out  = (float*)d_out_;
    float* csy  = out + CSY_OFF;
    float* irec = out + IR_OFF;

    float* fA = nullptr; float* fB = nullptr;
    cudaGetSymbolAddress((void**)&fA, g_featA);
    cudaGetSymbolAddress((void**)&fB, g_featB);

    // opt-in shared memory sizes
    cudaFuncSetAttribute(cs_k,     cudaFuncAttributeMaxDynamicSharedMemorySize, (8192 + 16384) * 4);
    cudaFuncSetAttribute(init_k,   cudaFuncAttributeMaxDynamicSharedMemorySize, 16384 * 4);
    cudaFuncSetAttribute(conv3x3_k,cudaFuncAttributeMaxDynamicSharedMemorySize, (64 * 576 + 396) * 4);

    // 1) CS sampling -> outcsy (in d_out)
    cs_k<<<dim3(16, 8), 256, (8192 + 16384) * 4>>>(x, Wcs, csy);

    // 2) 1x1 init conv + depth-to-space -> out_initrec (in d_out)
    init_k<<<dim3(16, 4), 256, 16384 * 4>>>(csy, Wi, irec);

    // 3) first conv 1->64 + PReLU(a_main) -> featA
    conv3x3_k<<<dim3(4, 64, 16), 256, (1 * 576 + 396) * 4>>>(
        irec, Wf, nullptr, am, fA, 1, F_PRELU);

    // 4) 4x residual blocks with shared weights
    const size_t smem64 = (size_t)(64 * 576 + 396) * 4;
    for (int b = 0; b < 4; b++) {
        conv3x3_k<<<dim3(4, 64, 16), 256, smem64>>>(
            fA, Wb, nullptr, ab, fB, 64, F_PRELU);
        conv3x3_k<<<dim3(4, 64, 16), 256, smem64>>>(
            fB, Wb, fA, ab, fA, 64, F_PRELU | F_RES);
    }

    // 5) last conv (feat + broadcast initrec) 64->1 -> out
    last_k<<<dim3(2, 16, 16), 256>>>(fA, irec, Wl, out);
}